// round 14
// baseline (speedup 1.0000x reference)
#include <cuda_runtime.h>
#include <cstdint>

#define TT 512
#define BB 256
#define HH 64
#define GG 256     // 4*H
#define RROWS 2    // batch rows per CTA -> 128 CTAs

// Scratch (device globals; no allocation in kernel_launch)
__device__ float g_hA[(size_t)TT * BB * HH];   // [T][B][H]
__device__ float g_hB[(size_t)TT * BB * HH];

// ---- packed fp32x2 helpers (Blackwell FFMA2 via PTX) ----------------------
__device__ __forceinline__ unsigned long long ffma2(unsigned long long a,
                                                    unsigned long long b,
                                                    unsigned long long c) {
    unsigned long long d;
    asm("fma.rn.f32x2 %0, %1, %2, %3;" : "=l"(d) : "l"(a), "l"(b), "l"(c));
    return d;
}
__device__ __forceinline__ unsigned long long fadd2(unsigned long long a,
                                                    unsigned long long b) {
    unsigned long long d;
    asm("add.rn.f32x2 %0, %1, %2;" : "=l"(d) : "l"(a), "l"(b));
    return d;
}
__device__ __forceinline__ float2 unpack2(unsigned long long v) {
    float2 r;
    asm("mov.b64 {%0, %1}, %2;" : "=f"(r.x), "=f"(r.y) : "l"(v));
    return r;
}
__device__ __forceinline__ unsigned long long pack2(float lo, float hi) {
    unsigned long long d;
    asm("mov.b64 %0, {%1, %2};" : "=l"(d) : "f"(lo), "f"(hi));
    return d;
}
// single-MUFU tanh (sm_75+)
__device__ __forceinline__ float tanh_approx(float x) {
    float y;
    asm("tanh.approx.f32 %0, %1;" : "=f"(y) : "f"(x));
    return y;
}
__device__ __forceinline__ float sig_approx(float x) {
    return fmaf(tanh_approx(x * 0.5f), 0.5f, 0.5f);
}

// ---------------------------------------------------------------------------
// Warp-specialized fused LSTM layer. 512 threads, grid = 128 (2 rows/CTA).
//   warps 0-7  (consumers): serial path only -> gates = gxr + W_hh.h[t-1]
//   warps 8-15 (producers): dependency-free W_ih.x[t] + bias, one step AHEAD,
//                           into 2-slot smem ring gxr (slot parity = step&1).
// Thread mapping in each group: (hidden j = warp*8 + l%8, k-quarter kq = l/8),
// both batch rows per thread. Reduce over kq: shfl.xor 8 then 16 (packed).
// MODE 0: layer 0, x = [B][T][2] (producer does the trivial 2-wide projection)
// MODE 1: layers 1-4, x = h_prev [T][B][64] staged via 4-slot smem ring +
//         4-deep per-thread LDG pipeline (producers' lower 128 threads).
// One __syncthreads per step (all 16 warps, lockstep; slot parity decouples).
// ---------------------------------------------------------------------------
template <int MODE>
__global__ __launch_bounds__(512, 1) void lstm_rec_ws(
    const float* __restrict__ xin,    // MODE0: x [B][T][2]; MODE1: h_prev [T][B][64]
    const float* __restrict__ Whh,    // [256][64]
    const float* __restrict__ Wih,    // MODE0: [256][2]; MODE1: [256][64]
    const float* __restrict__ bih,    // [256]
    const float* __restrict__ bhh,    // [256]
    float* __restrict__ hout)         // [T][B][64]
{
    __shared__ __align__(16) float h_s[2][RROWS * HH];
    __shared__ __align__(16) float gxr[2][RROWS][GG];     // gate partials ring
    __shared__ __align__(16) float xring[4][RROWS * HH];  // MODE1 x stage
    const int tid = threadIdx.x;
    const bool cons = tid < 256;
    const int t2 = tid & 255;
    const int l = t2 & 31;
    const int w = t2 >> 5;            // warp-in-group 0..7 = j_high
    const int kq = l >> 3;            // k-quarter
    const int j = w * 8 + (l & 7);    // hidden index 0..63
    const int row0 = blockIdx.x * RROWS;
    const unsigned fm = 0xffffffffu;

    if (cons) {
        // ------------------------- CONSUMER ------------------------------
        unsigned long long whh[4][8];
#pragma unroll
        for (int g = 0; g < 4; g++) {
            const double2* hp =
                reinterpret_cast<const double2*>(Whh + (size_t)(g * 64 + j) * HH);
#pragma unroll
            for (int i = 0; i < 4; i++) {
                double2 d = hp[4 * i + kq];
                whh[g][2 * i]     = __double_as_longlong(d.x);
                whh[g][2 * i + 1] = __double_as_longlong(d.y);
            }
        }
        float c0 = 0.0f, c1 = 0.0f;
        if (t2 < RROWS * HH) h_s[0][t2] = 0.0f;
        __syncthreads();   // P1: setup done
        __syncthreads();   // P2: producers filled gxr slot 0

#pragma unroll 4
        for (int t = 0; t < TT; t++) {
            const int p = t & 1;
            unsigned long long ah[4][2];
#pragma unroll
            for (int g = 0; g < 4; g++) { ah[g][0] = 0ull; ah[g][1] = 0ull; }
            const ulonglong2* hb0 = reinterpret_cast<const ulonglong2*>(h_s[p]);
            const ulonglong2* hb1 = reinterpret_cast<const ulonglong2*>(h_s[p] + HH);
#pragma unroll
            for (int i = 0; i < 4; i++) {
                const int ch = 4 * i + kq;
                ulonglong2 h0 = hb0[ch];
                ulonglong2 h1 = hb1[ch];
#pragma unroll
                for (int g = 0; g < 4; g++) {
                    ah[g][0] = ffma2(whh[g][2 * i], h0.x, ah[g][0]);
                    ah[g][0] = ffma2(whh[g][2 * i + 1], h0.y, ah[g][0]);
                    ah[g][1] = ffma2(whh[g][2 * i], h1.x, ah[g][1]);
                    ah[g][1] = ffma2(whh[g][2 * i + 1], h1.y, ah[g][1]);
                }
            }
            float s[4][2];
#pragma unroll
            for (int g = 0; g < 4; g++) {
#pragma unroll
                for (int r = 0; r < 2; r++) {
                    float2 u = unpack2(ah[g][r]);
                    s[g][r] = u.x + u.y;
                }
            }
            unsigned long long pr0a = pack2(s[0][0], s[1][0]);
            unsigned long long pr0b = pack2(s[2][0], s[3][0]);
            unsigned long long pr1a = pack2(s[0][1], s[1][1]);
            unsigned long long pr1b = pack2(s[2][1], s[3][1]);
            pr0a = fadd2(pr0a, __shfl_xor_sync(fm, pr0a, 8, 32));
            pr0b = fadd2(pr0b, __shfl_xor_sync(fm, pr0b, 8, 32));
            pr1a = fadd2(pr1a, __shfl_xor_sync(fm, pr1a, 8, 32));
            pr1b = fadd2(pr1b, __shfl_xor_sync(fm, pr1b, 8, 32));
            pr0a = fadd2(pr0a, __shfl_xor_sync(fm, pr0a, 16, 32));
            pr0b = fadd2(pr0b, __shfl_xor_sync(fm, pr0b, 16, 32));
            pr1a = fadd2(pr1a, __shfl_xor_sync(fm, pr1a, 16, 32));
            pr1b = fadd2(pr1b, __shfl_xor_sync(fm, pr1b, 16, 32));
            float2 r0a = unpack2(pr0a), r0b = unpack2(pr0b);
            float2 r1a = unpack2(pr1a), r1b = unpack2(pr1b);

            const float4 gv0 = *reinterpret_cast<const float4*>(&gxr[p][0][4 * j]);
            const float4 gv1 = *reinterpret_cast<const float4*>(&gxr[p][1][4 * j]);

            const float ig0 = sig_approx(r0a.x + gv0.x);
            const float fg0 = sig_approx(r0a.y + gv0.y);
            const float Gg0 = tanh_approx(r0b.x + gv0.z);
            const float og0 = sig_approx(r0b.y + gv0.w);
            const float ig1 = sig_approx(r1a.x + gv1.x);
            const float fg1 = sig_approx(r1a.y + gv1.y);
            const float Gg1 = tanh_approx(r1b.x + gv1.z);
            const float og1 = sig_approx(r1b.y + gv1.w);

            c0 = fmaf(fg0, c0, ig0 * Gg0);
            c1 = fmaf(fg1, c1, ig1 * Gg1);
            const float h0 = og0 * tanh_approx(c0);
            const float h1 = og1 * tanh_approx(c1);

            if (kq == 0) {
                h_s[p ^ 1][j]      = h0;
                h_s[p ^ 1][HH + j] = h1;
                hout[((size_t)t * BB + row0) * HH + j]     = h0;
                hout[((size_t)t * BB + row0 + 1) * HH + j] = h1;
            }
            __syncthreads();
        }
    } else if (MODE == 1) {
        // ------------------------- PRODUCER (d_in = 64) -------------------
        unsigned long long wih[4][8];
        float bs[4];
#pragma unroll
        for (int g = 0; g < 4; g++) {
            const double2* ip =
                reinterpret_cast<const double2*>(Wih + (size_t)(g * 64 + j) * HH);
#pragma unroll
            for (int i = 0; i < 4; i++) {
                double2 d = ip[4 * i + kq];
                wih[g][2 * i]     = __double_as_longlong(d.x);
                wih[g][2 * i + 1] = __double_as_longlong(d.y);
            }
            bs[g] = bih[g * 64 + j] + bhh[g * 64 + j];
        }
        // x stager: lower 128 producer threads
        float v[4];
        const float* ldp = nullptr;
        if (t2 < RROWS * HH) {
            const int lrow = t2 >> 6, jj = t2 & 63;
            ldp = xin + (size_t)(row0 + lrow) * HH + jj;
            xring[0][t2] = __ldg(ldp + (size_t)0 * BB * HH);
            xring[1][t2] = __ldg(ldp + (size_t)1 * BB * HH);
            xring[2][t2] = __ldg(ldp + (size_t)2 * BB * HH);
#pragma unroll
            for (int i = 0; i < 4; i++)
                v[i] = __ldg(ldp + (size_t)(3 + i) * BB * HH);
        }
        __syncthreads();   // P1
        // prologue: produce step 0 from xring[0]
        {
            unsigned long long ai[4][2];
#pragma unroll
            for (int g = 0; g < 4; g++) { ai[g][0] = 0ull; ai[g][1] = 0ull; }
            const ulonglong2* xb0 = reinterpret_cast<const ulonglong2*>(xring[0]);
            const ulonglong2* xb1 = reinterpret_cast<const ulonglong2*>(xring[0] + HH);
#pragma unroll
            for (int i = 0; i < 4; i++) {
                const int ch = 4 * i + kq;
                ulonglong2 x0 = xb0[ch];
                ulonglong2 x1 = xb1[ch];
#pragma unroll
                for (int g = 0; g < 4; g++) {
                    ai[g][0] = ffma2(wih[g][2 * i], x0.x, ai[g][0]);
                    ai[g][0] = ffma2(wih[g][2 * i + 1], x0.y, ai[g][0]);
                    ai[g][1] = ffma2(wih[g][2 * i], x1.x, ai[g][1]);
                    ai[g][1] = ffma2(wih[g][2 * i + 1], x1.y, ai[g][1]);
                }
            }
            float s[4][2];
#pragma unroll
            for (int g = 0; g < 4; g++)
#pragma unroll
                for (int r = 0; r < 2; r++) {
                    float2 u = unpack2(ai[g][r]);
                    s[g][r] = u.x + u.y;
                }
            unsigned long long pr0a = pack2(s[0][0], s[1][0]);
            unsigned long long pr0b = pack2(s[2][0], s[3][0]);
            unsigned long long pr1a = pack2(s[0][1], s[1][1]);
            unsigned long long pr1b = pack2(s[2][1], s[3][1]);
            pr0a = fadd2(pr0a, __shfl_xor_sync(fm, pr0a, 8, 32));
            pr0b = fadd2(pr0b, __shfl_xor_sync(fm, pr0b, 8, 32));
            pr1a = fadd2(pr1a, __shfl_xor_sync(fm, pr1a, 8, 32));
            pr1b = fadd2(pr1b, __shfl_xor_sync(fm, pr1b, 8, 32));
            pr0a = fadd2(pr0a, __shfl_xor_sync(fm, pr0a, 16, 32));
            pr0b = fadd2(pr0b, __shfl_xor_sync(fm, pr0b, 16, 32));
            pr1a = fadd2(pr1a, __shfl_xor_sync(fm, pr1a, 16, 32));
            pr1b = fadd2(pr1b, __shfl_xor_sync(fm, pr1b, 16, 32));
            if (kq == 0) {
                float2 r0a = unpack2(pr0a), r0b = unpack2(pr0b);
                float2 r1a = unpack2(pr1a), r1b = unpack2(pr1b);
                *reinterpret_cast<float4*>(&gxr[0][0][4 * j]) =
                    make_float4(r0a.x + bs[0], r0a.y + bs[1], r0b.x + bs[2], r0b.y + bs[3]);
                *reinterpret_cast<float4*>(&gxr[0][1][4 * j]) =
                    make_float4(r1a.x + bs[0], r1a.y + bs[1], r1b.x + bs[2], r1b.y + bs[3]);
            }
        }
        __syncthreads();   // P2

#pragma unroll 4
        for (int t = 0; t < TT; t++) {
            // stage x[t+3] into its slot; refill pipeline with x[t+7]
            if (t2 < RROWS * HH) {
                xring[(t + 3) & 3][t2] = v[t & 3];
                if (t + 7 < TT)
                    v[t & 3] = __ldg(ldp + (size_t)(t + 7) * BB * HH);
            }
            const int tp = t + 1;
            if (tp < TT) {
                unsigned long long ai[4][2];
#pragma unroll
                for (int g = 0; g < 4; g++) { ai[g][0] = 0ull; ai[g][1] = 0ull; }
                const ulonglong2* xb0 =
                    reinterpret_cast<const ulonglong2*>(xring[tp & 3]);
                const ulonglong2* xb1 =
                    reinterpret_cast<const ulonglong2*>(xring[tp & 3] + HH);
#pragma unroll
                for (int i = 0; i < 4; i++) {
                    const int ch = 4 * i + kq;
                    ulonglong2 x0 = xb0[ch];
                    ulonglong2 x1 = xb1[ch];
#pragma unroll
                    for (int g = 0; g < 4; g++) {
                        ai[g][0] = ffma2(wih[g][2 * i], x0.x, ai[g][0]);
                        ai[g][0] = ffma2(wih[g][2 * i + 1], x0.y, ai[g][0]);
                        ai[g][1] = ffma2(wih[g][2 * i], x1.x, ai[g][1]);
                        ai[g][1] = ffma2(wih[g][2 * i + 1], x1.y, ai[g][1]);
                    }
                }
                float s[4][2];
#pragma unroll
                for (int g = 0; g < 4; g++)
#pragma unroll
                    for (int r = 0; r < 2; r++) {
                        float2 u = unpack2(ai[g][r]);
                        s[g][r] = u.x + u.y;
                    }
                unsigned long long pr0a = pack2(s[0][0], s[1][0]);
                unsigned long long pr0b = pack2(s[2][0], s[3][0]);
                unsigned long long pr1a = pack2(s[0][1], s[1][1]);
                unsigned long long pr1b = pack2(s[2][1], s[3][1]);
                pr0a = fadd2(pr0a, __shfl_xor_sync(fm, pr0a, 8, 32));
                pr0b = fadd2(pr0b, __shfl_xor_sync(fm, pr0b, 8, 32));
                pr1a = fadd2(pr1a, __shfl_xor_sync(fm, pr1a, 8, 32));
                pr1b = fadd2(pr1b, __shfl_xor_sync(fm, pr1b, 8, 32));
                pr0a = fadd2(pr0a, __shfl_xor_sync(fm, pr0a, 16, 32));
                pr0b = fadd2(pr0b, __shfl_xor_sync(fm, pr0b, 16, 32));
                pr1a = fadd2(pr1a, __shfl_xor_sync(fm, pr1a, 16, 32));
                pr1b = fadd2(pr1b, __shfl_xor_sync(fm, pr1b, 16, 32));
                if (kq == 0) {
                    float2 r0a = unpack2(pr0a), r0b = unpack2(pr0b);
                    float2 r1a = unpack2(pr1a), r1b = unpack2(pr1b);
                    *reinterpret_cast<float4*>(&gxr[tp & 1][0][4 * j]) =
                        make_float4(r0a.x + bs[0], r0a.y + bs[1],
                                    r0b.x + bs[2], r0b.y + bs[3]);
                    *reinterpret_cast<float4*>(&gxr[tp & 1][1][4 * j]) =
                        make_float4(r1a.x + bs[0], r1a.y + bs[1],
                                    r1b.x + bs[2], r1b.y + bs[3]);
                }
            }
            __syncthreads();
        }
    } else {
        // ------------------------- PRODUCER (layer 0, d_in = 2) ----------
        float2 w2[4];
        float bs[4];
#pragma unroll
        for (int g = 0; g < 4; g++) {
            w2[g] = *reinterpret_cast<const float2*>(Wih + (size_t)(g * 64 + j) * 2);
            bs[g] = bih[g * 64 + j] + bhh[g * 64 + j];
        }
        __syncthreads();   // P1
        if (kq == 0) {
            const float2 xv0 = __ldg(reinterpret_cast<const float2*>(
                xin + ((size_t)(row0 + 0) * TT + 0) * 2));
            const float2 xv1 = __ldg(reinterpret_cast<const float2*>(
                xin + ((size_t)(row0 + 1) * TT + 0) * 2));
            *reinterpret_cast<float4*>(&gxr[0][0][4 * j]) = make_float4(
                bs[0] + xv0.x * w2[0].x + xv0.y * w2[0].y,
                bs[1] + xv0.x * w2[1].x + xv0.y * w2[1].y,
                bs[2] + xv0.x * w2[2].x + xv0.y * w2[2].y,
                bs[3] + xv0.x * w2[3].x + xv0.y * w2[3].y);
            *reinterpret_cast<float4*>(&gxr[0][1][4 * j]) = make_float4(
                bs[0] + xv1.x * w2[0].x + xv1.y * w2[0].y,
                bs[1] + xv1.x * w2[1].x + xv1.y * w2[1].y,
                bs[2] + xv1.x * w2[2].x + xv1.y * w2[2].y,
                bs[3] + xv1.x * w2[3].x + xv1.y * w2[3].y);
        }
        __syncthreads();   // P2
#pragma unroll 4
        for (int t = 0; t < TT; t++) {
            const int tp = t + 1;
            if (tp < TT && kq == 0) {
                const float2 xv0 = __ldg(reinterpret_cast<const float2*>(
                    xin + ((size_t)(row0 + 0) * TT + tp) * 2));
                const float2 xv1 = __ldg(reinterpret_cast<const float2*>(
                    xin + ((size_t)(row0 + 1) * TT + tp) * 2));
                *reinterpret_cast<float4*>(&gxr[tp & 1][0][4 * j]) = make_float4(
                    bs[0] + xv0.x * w2[0].x + xv0.y * w2[0].y,
                    bs[1] + xv0.x * w2[1].x + xv0.y * w2[1].y,
                    bs[2] + xv0.x * w2[2].x + xv0.y * w2[2].y,
                    bs[3] + xv0.x * w2[3].x + xv0.y * w2[3].y);
                *reinterpret_cast<float4*>(&gxr[tp & 1][1][4 * j]) = make_float4(
                    bs[0] + xv1.x * w2[0].x + xv1.y * w2[0].y,
                    bs[1] + xv1.x * w2[1].x + xv1.y * w2[1].y,
                    bs[2] + xv1.x * w2[2].x + xv1.y * w2[2].y,
                    bs[3] + xv1.x * w2[3].x + xv1.y * w2[3].y);
            }
            __syncthreads();
        }
    }
}

// ---------------------------------------------------------------------------
// Final linear head. grid = T, block = 256.
// ---------------------------------------------------------------------------
__global__ __launch_bounds__(256) void lstm_lin_kernel(
    const float* __restrict__ hseq,   // [T][B][64]
    const float* __restrict__ Wl,     // [64]
    const float* __restrict__ bl,     // [1]
    float* __restrict__ out)          // [B][T]
{
    __shared__ float4 wl4[16];
    const int t = blockIdx.x;
    const int b = threadIdx.x;
    if (threadIdx.x < 16)
        wl4[threadIdx.x] = reinterpret_cast<const float4*>(Wl)[threadIdx.x];
    __syncthreads();

    const float4* hp = reinterpret_cast<const float4*>(hseq + ((size_t)t * BB + b) * HH);
    float acc = bl[0];
#pragma unroll
    for (int k4 = 0; k4 < 16; k4++) {
        const float4 h = hp[k4];
        const float4 w = wl4[k4];
        acc = fmaf(h.x, w.x, acc);
        acc = fmaf(h.y, w.y, acc);
        acc = fmaf(h.z, w.z, acc);
        acc = fmaf(h.w, w.w, acc);
    }
    out[(size_t)b * TT + t] = acc;
}

// ---------------------------------------------------------------------------
extern "C" void kernel_launch(void* const* d_in, const int* in_sizes, int n_in,
                              void* d_out, int out_size)
{
    (void)in_sizes; (void)n_in; (void)out_size;

    const float* x = (const float*)d_in[0];
    const float* Wih[5]; const float* Whh[5]; const float* bih[5]; const float* bhh[5];
    for (int l = 0; l < 5; l++) {
        Wih[l] = (const float*)d_in[1 + 4 * l];
        Whh[l] = (const float*)d_in[2 + 4 * l];
        bih[l] = (const float*)d_in[3 + 4 * l];
        bhh[l] = (const float*)d_in[4 + 4 * l];
    }
    const float* Wl = (const float*)d_in[21];
    const float* bl = (const float*)d_in[22];
    float* out = (float*)d_out;

    float *hA, *hB;
    cudaGetSymbolAddress((void**)&hA, g_hA);
    cudaGetSymbolAddress((void**)&hB, g_hB);
    float* bufs[2] = { hA, hB };

    // layer 0: fully fused (trivial d_in=2 producer)
    lstm_rec_ws<0><<<BB / RROWS, 512>>>(x, Whh[0], Wih[0], bih[0], bhh[0], bufs[0]);

    // layers 1..4: warp-specialized fused
    for (int l = 1; l < 5; l++) {
        const float* hin = bufs[(l - 1) & 1];
        float* ho = bufs[l & 1];
        lstm_rec_ws<1><<<BB / RROWS, 512>>>(hin, Whh[l], Wih[l], bih[l], bhh[l], ho);
    }

    // linear head (layer 4 wrote bufs[0])
    lstm_lin_kernel<<<TT, 256>>>(bufs[0], Wl, bl, out);
}

// round 15
// speedup vs baseline: 1.0766x; 1.0766x over previous
#include <cuda_runtime.h>
#include <cstdint>

#define TT 512
#define BB 256
#define HH 64
#define GG 256     // 4*H
#define RROWS 2    // batch rows per recurrence CTA -> 128 CTAs
#define PF 8       // MODE0 gx prefetch depth; keep '#pragma unroll 8' in sync
static_assert(PF == 8, "update '#pragma unroll 8' in lstm_rec_fused if PF changes");

// Scratch (device globals; no allocation in kernel_launch)
__device__ float g_gx[(size_t)TT * BB * GG];   // [T][B][4H] permuted (layer 0 only)
__device__ float g_hA[(size_t)TT * BB * HH];   // [T][B][H]
__device__ float g_hB[(size_t)TT * BB * HH];

// ---- packed fp32x2 helpers (Blackwell FFMA2 via PTX) ----------------------
__device__ __forceinline__ unsigned long long ffma2(unsigned long long a,
                                                    unsigned long long b,
                                                    unsigned long long c) {
    unsigned long long d;
    asm("fma.rn.f32x2 %0, %1, %2, %3;" : "=l"(d) : "l"(a), "l"(b), "l"(c));
    return d;
}
__device__ __forceinline__ unsigned long long fadd2(unsigned long long a,
                                                    unsigned long long b) {
    unsigned long long d;
    asm("add.rn.f32x2 %0, %1, %2;" : "=l"(d) : "l"(a), "l"(b));
    return d;
}
__device__ __forceinline__ float2 unpack2(unsigned long long v) {
    float2 r;
    asm("mov.b64 {%0, %1}, %2;" : "=f"(r.x), "=f"(r.y) : "l"(v));
    return r;
}
__device__ __forceinline__ unsigned long long pack2(float lo, float hi) {
    unsigned long long d;
    asm("mov.b64 %0, {%1, %2};" : "=l"(d) : "f"(lo), "f"(hi));
    return d;
}
// single-MUFU tanh (sm_75+)
__device__ __forceinline__ float tanh_approx(float x) {
    float y;
    asm("tanh.approx.f32 %0, %1;" : "=f"(y) : "f"(x));
    return y;
}
__device__ __forceinline__ float sig_approx(float x) {
    return fmaf(tanh_approx(x * 0.5f), 0.5f, 0.5f);
}

// gate slot permutation: slot q <-> (j = q>>2, g = q&3), torch row = g*64+j
__device__ __forceinline__ int perm_row(int q) { return (q & 3) * 64 + (q >> 2); }

// ---------------------------------------------------------------------------
// Layer 0 input projection (d_in = 2), writes permuted gx layout.
// grid = T, block = 256
// ---------------------------------------------------------------------------
__global__ __launch_bounds__(256) void lstm_gx0_kernel(
    const float* __restrict__ x,      // [B][T][2]
    const float* __restrict__ Wih,    // [256][2]
    const float* __restrict__ bih,
    const float* __restrict__ bhh,
    float* __restrict__ gxout)        // [T][B][256] permuted
{
    __shared__ float xs[2 * BB];
    const int t = blockIdx.x;
    const int tid = threadIdx.x;
    const int wr = perm_row(tid);

    xs[2 * tid]     = x[((size_t)tid * TT + t) * 2 + 0];
    xs[2 * tid + 1] = x[((size_t)tid * TT + t) * 2 + 1];
    const float w0   = Wih[wr * 2];
    const float w1   = Wih[wr * 2 + 1];
    const float bias = bih[wr] + bhh[wr];
    __syncthreads();

    float* op = gxout + (size_t)t * BB * GG + tid;
#pragma unroll 4
    for (int r = 0; r < BB; r++) {
        op[r * GG] = fmaf(xs[2 * r], w0, fmaf(xs[2 * r + 1], w1, bias));
    }
}

// ---------------------------------------------------------------------------
// Fused recurrence (R13 structure + one-step-shifted ih pipeline).
// 256 threads, 2 batch rows per CTA, grid = 128.
// Thread = (hidden j, k-quarter kq): all 4 gates of j over 16 of 64 k, both
// rows. Reduce over kq: shfl.xor 8 then 16 (packed f32x2).
// MODE 0 (layer 0): gates = gx(precomputed, 8-deep float4 ring) + W_hh.h
// MODE 1 (layers 1-4): gates = bias + W_ih.x[t] + W_hh.h[t-1], where the
//   W_ih.x dot for step t+1 is computed DURING step t's reduce/activation
//   tail (it only needs the x ring) -> fills the FMA-pipe bubble and drops
//   ih off the serial critical path. ai double-buffered by step parity.
// One __syncthreads per step.
// ---------------------------------------------------------------------------
template <int MODE>
__global__ __launch_bounds__(256, 1) void lstm_rec_fused(
    const float* __restrict__ xin,    // MODE0: gx [T][B][256]; MODE1: h_prev [T][B][64]
    const float* __restrict__ Whh,    // [256][64]
    const float* __restrict__ Wih,    // [256][64]  (MODE1)
    const float* __restrict__ bih,    // [256]      (MODE1)
    const float* __restrict__ bhh,    // [256]      (MODE1)
    float* __restrict__ hout)         // [T][B][64]
{
    __shared__ __align__(16) float h_s[2][RROWS * HH];
    __shared__ __align__(16) float ring[4][RROWS * HH];   // MODE1 x stage
    const int tid = threadIdx.x;
    const int l = tid & 31;
    const int w = tid >> 5;           // warp 0..7 = j_high
    const int kq = l >> 3;            // k-quarter 0..3
    const int j = w * 8 + (l & 7);    // hidden index 0..63
    const int row0 = blockIdx.x * RROWS;
    const unsigned fm = 0xffffffffu;

    // Weights: per gate g (torch row g*64+j), chunks c = 4*i + kq (i=0..3).
    unsigned long long whh[4][8], wih[4][8];
    float bias[4];
#pragma unroll
    for (int g = 0; g < 4; g++) {
        const double2* hp = reinterpret_cast<const double2*>(Whh + (size_t)(g * 64 + j) * HH);
#pragma unroll
        for (int i = 0; i < 4; i++) {
            double2 d = hp[4 * i + kq];
            whh[g][2 * i]     = __double_as_longlong(d.x);
            whh[g][2 * i + 1] = __double_as_longlong(d.y);
        }
        if (MODE == 1) {
            const double2* ip = reinterpret_cast<const double2*>(Wih + (size_t)(g * 64 + j) * HH);
#pragma unroll
            for (int i = 0; i < 4; i++) {
                double2 d = ip[4 * i + kq];
                wih[g][2 * i]     = __double_as_longlong(d.x);
                wih[g][2 * i + 1] = __double_as_longlong(d.y);
            }
            bias[g] = bih[g * 64 + j] + bhh[g * 64 + j];
        } else {
            bias[g] = 0.0f;
        }
    }

    float c0 = 0.0f, c1 = 0.0f;
    if (tid < RROWS * HH) h_s[0][tid] = 0.0f;

    // MODE0: gx register rings; MODE1: x-stager state (threads 0..127)
    float4 gr0[PF], gr1[PF];
    const float4* gxp0 = nullptr; const float4* gxp1 = nullptr;
    float v[4];
    const float* ldp = nullptr;
    if (MODE == 0) {
        gxp0 = reinterpret_cast<const float4*>(xin + (size_t)row0 * GG + 4 * j);
        gxp1 = reinterpret_cast<const float4*>(xin + (size_t)(row0 + 1) * GG + 4 * j);
#pragma unroll
        for (int i = 0; i < PF; i++) {
            gr0[i] = __ldg(gxp0 + (size_t)i * (BB * GG / 4));
            gr1[i] = __ldg(gxp1 + (size_t)i * (BB * GG / 4));
        }
    } else if (tid < RROWS * HH) {
        const int lrow = tid >> 6, jj = tid & 63;
        ldp = xin + (size_t)(row0 + lrow) * HH + jj;
        ring[0][tid] = __ldg(ldp + (size_t)0 * BB * HH);
        ring[1][tid] = __ldg(ldp + (size_t)1 * BB * HH);
#pragma unroll
        for (int i = 0; i < 4; i++)
            v[i] = __ldg(ldp + (size_t)(2 + i) * BB * HH);
    }
    __syncthreads();

    // MODE1 prologue: ai for step 0 (parity buffer 0) from ring[0]
    unsigned long long aib[2][4][2];
#pragma unroll
    for (int b2 = 0; b2 < 2; b2++)
#pragma unroll
        for (int g = 0; g < 4; g++) { aib[b2][g][0] = 0ull; aib[b2][g][1] = 0ull; }
    if (MODE == 1) {
        const ulonglong2* xb0 = reinterpret_cast<const ulonglong2*>(ring[0]);
        const ulonglong2* xb1 = reinterpret_cast<const ulonglong2*>(ring[0] + HH);
#pragma unroll
        for (int i = 0; i < 4; i++) {
            const int ch = 4 * i + kq;
            ulonglong2 x0 = xb0[ch];
            ulonglong2 x1 = xb1[ch];
#pragma unroll
            for (int g = 0; g < 4; g++) {
                aib[0][g][0] = ffma2(wih[g][2 * i], x0.x, aib[0][g][0]);
                aib[0][g][0] = ffma2(wih[g][2 * i + 1], x0.y, aib[0][g][0]);
                aib[0][g][1] = ffma2(wih[g][2 * i], x1.x, aib[0][g][1]);
                aib[0][g][1] = ffma2(wih[g][2 * i + 1], x1.y, aib[0][g][1]);
            }
        }
    }

#pragma unroll 8
    for (int t = 0; t < TT; t++) {
        const int p = t & 1;

        float4 gxv0, gxv1;
        if (MODE == 0) {
            const int slot = t & (PF - 1);
            gxv0 = gr0[slot]; gxv1 = gr1[slot];
            if (t + PF < TT) {
                gr0[slot] = __ldg(gxp0 + (size_t)(t + PF) * (BB * GG / 4));
                gr1[slot] = __ldg(gxp1 + (size_t)(t + PF) * (BB * GG / 4));
            }
        } else if (tid < RROWS * HH) {
            // stage x[t+2] into its slot; refill reg pipeline with x[t+6]
            ring[(t + 2) & 3][tid] = v[t & 3];
            if (t + 6 < TT)
                v[t & 3] = __ldg(ldp + (size_t)(t + 6) * BB * HH);
        }

        // serial half: ah = W_hh . h[t-1]
        unsigned long long ah[4][2];
#pragma unroll
        for (int g = 0; g < 4; g++) { ah[g][0] = 0ull; ah[g][1] = 0ull; }
        {
            const ulonglong2* hb0 = reinterpret_cast<const ulonglong2*>(h_s[p]);
            const ulonglong2* hb1 = reinterpret_cast<const ulonglong2*>(h_s[p] + HH);
#pragma unroll
            for (int i = 0; i < 4; i++) {
                const int ch = 4 * i + kq;
                ulonglong2 h0 = hb0[ch];
                ulonglong2 h1 = hb1[ch];
#pragma unroll
                for (int g = 0; g < 4; g++) {
                    ah[g][0] = ffma2(whh[g][2 * i], h0.x, ah[g][0]);
                    ah[g][0] = ffma2(whh[g][2 * i + 1], h0.y, ah[g][0]);
                    ah[g][1] = ffma2(whh[g][2 * i], h1.x, ah[g][1]);
                    ah[g][1] = ffma2(whh[g][2 * i + 1], h1.y, ah[g][1]);
                }
            }
        }

        // independent half for NEXT step: ai(t+1) = W_ih . x[t+1].
        // Issued here so its FFMA2s drain into the reduce/MUFU stall bubbles.
        if (MODE == 1 && t + 1 < TT) {
            const int nb = (t + 1) & 1;
#pragma unroll
            for (int g = 0; g < 4; g++) { aib[nb][g][0] = 0ull; aib[nb][g][1] = 0ull; }
            const ulonglong2* xb0 =
                reinterpret_cast<const ulonglong2*>(ring[(t + 1) & 3]);
            const ulonglong2* xb1 =
                reinterpret_cast<const ulonglong2*>(ring[(t + 1) & 3] + HH);
#pragma unroll
            for (int i = 0; i < 4; i++) {
                const int ch = 4 * i + kq;
                ulonglong2 x0 = xb0[ch];
                ulonglong2 x1 = xb1[ch];
#pragma unroll
                for (int g = 0; g < 4; g++) {
                    aib[nb][g][0] = ffma2(wih[g][2 * i], x0.x, aib[nb][g][0]);
                    aib[nb][g][0] = ffma2(wih[g][2 * i + 1], x0.y, aib[nb][g][0]);
                    aib[nb][g][1] = ffma2(wih[g][2 * i], x1.x, aib[nb][g][1]);
                    aib[nb][g][1] = ffma2(wih[g][2 * i + 1], x1.y, aib[nb][g][1]);
                }
            }
        }

        // combine current step's halves, reduce over kq, activate
        float s[4][2];
#pragma unroll
        for (int g = 0; g < 4; g++) {
#pragma unroll
            for (int r = 0; r < 2; r++) {
                float2 u = unpack2(MODE == 1 ? fadd2(ah[g][r], aib[p][g][r])
                                             : ah[g][r]);
                s[g][r] = u.x + u.y;
            }
        }
        unsigned long long pr0a = pack2(s[0][0], s[1][0]);  // row0 (i,f)
        unsigned long long pr0b = pack2(s[2][0], s[3][0]);  // row0 (g~,o)
        unsigned long long pr1a = pack2(s[0][1], s[1][1]);
        unsigned long long pr1b = pack2(s[2][1], s[3][1]);
        pr0a = fadd2(pr0a, __shfl_xor_sync(fm, pr0a, 8, 32));
        pr0b = fadd2(pr0b, __shfl_xor_sync(fm, pr0b, 8, 32));
        pr1a = fadd2(pr1a, __shfl_xor_sync(fm, pr1a, 8, 32));
        pr1b = fadd2(pr1b, __shfl_xor_sync(fm, pr1b, 8, 32));
        pr0a = fadd2(pr0a, __shfl_xor_sync(fm, pr0a, 16, 32));
        pr0b = fadd2(pr0b, __shfl_xor_sync(fm, pr0b, 16, 32));
        pr1a = fadd2(pr1a, __shfl_xor_sync(fm, pr1a, 16, 32));
        pr1b = fadd2(pr1b, __shfl_xor_sync(fm, pr1b, 16, 32));

        float2 r0a = unpack2(pr0a), r0b = unpack2(pr0b);
        float2 r1a = unpack2(pr1a), r1b = unpack2(pr1b);

        float vi0 = r0a.x + bias[0], vf0 = r0a.y + bias[1];
        float vg0 = r0b.x + bias[2], vo0 = r0b.y + bias[3];
        float vi1 = r1a.x + bias[0], vf1 = r1a.y + bias[1];
        float vg1 = r1b.x + bias[2], vo1 = r1b.y + bias[3];
        if (MODE == 0) {
            vi0 += gxv0.x; vf0 += gxv0.y; vg0 += gxv0.z; vo0 += gxv0.w;
            vi1 += gxv1.x; vf1 += gxv1.y; vg1 += gxv1.z; vo1 += gxv1.w;
        }

        const float ig0 = sig_approx(vi0), fg0 = sig_approx(vf0);
        const float Gg0 = tanh_approx(vg0), og0 = sig_approx(vo0);
        const float ig1 = sig_approx(vi1), fg1 = sig_approx(vf1);
        const float Gg1 = tanh_approx(vg1), og1 = sig_approx(vo1);

        c0 = fmaf(fg0, c0, ig0 * Gg0);
        c1 = fmaf(fg1, c1, ig1 * Gg1);
        const float h0 = og0 * tanh_approx(c0);
        const float h1 = og1 * tanh_approx(c1);

        if (kq == 0) {   // one writer per j (lanes 0..7 of each warp)
            h_s[p ^ 1][j]      = h0;
            h_s[p ^ 1][HH + j] = h1;
            hout[((size_t)t * BB + row0) * HH + j]     = h0;
            hout[((size_t)t * BB + row0 + 1) * HH + j] = h1;
        }
        __syncthreads();
    }
}

// ---------------------------------------------------------------------------
// Final linear head. grid = T, block = 256.
// ---------------------------------------------------------------------------
__global__ __launch_bounds__(256) void lstm_lin_kernel(
    const float* __restrict__ hseq,   // [T][B][64]
    const float* __restrict__ Wl,     // [64]
    const float* __restrict__ bl,     // [1]
    float* __restrict__ out)          // [B][T]
{
    __shared__ float4 wl4[16];
    const int t = blockIdx.x;
    const int b = threadIdx.x;
    if (threadIdx.x < 16)
        wl4[threadIdx.x] = reinterpret_cast<const float4*>(Wl)[threadIdx.x];
    __syncthreads();

    const float4* hp = reinterpret_cast<const float4*>(hseq + ((size_t)t * BB + b) * HH);
    float acc = bl[0];
#pragma unroll
    for (int k4 = 0; k4 < 16; k4++) {
        const float4 h = hp[k4];
        const float4 w = wl4[k4];
        acc = fmaf(h.x, w.x, acc);
        acc = fmaf(h.y, w.y, acc);
        acc = fmaf(h.z, w.z, acc);
        acc = fmaf(h.w, w.w, acc);
    }
    out[(size_t)b * TT + t] = acc;
}

// ---------------------------------------------------------------------------
extern "C" void kernel_launch(void* const* d_in, const int* in_sizes, int n_in,
                              void* d_out, int out_size)
{
    (void)in_sizes; (void)n_in; (void)out_size;

    const float* x = (const float*)d_in[0];
    const float* Wih[5]; const float* Whh[5]; const float* bih[5]; const float* bhh[5];
    for (int l = 0; l < 5; l++) {
        Wih[l] = (const float*)d_in[1 + 4 * l];
        Whh[l] = (const float*)d_in[2 + 4 * l];
        bih[l] = (const float*)d_in[3 + 4 * l];
        bhh[l] = (const float*)d_in[4 + 4 * l];
    }
    const float* Wl = (const float*)d_in[21];
    const float* bl = (const float*)d_in[22];
    float* out = (float*)d_out;

    float *gx, *hA, *hB;
    cudaGetSymbolAddress((void**)&gx, g_gx);
    cudaGetSymbolAddress((void**)&hA, g_hA);
    cudaGetSymbolAddress((void**)&hB, g_hB);
    float* bufs[2] = { hA, hB };

    // layer 0: tiny input projection + MODE0 recurrence
    lstm_gx0_kernel<<<TT, 256>>>(x, Wih[0], bih[0], bhh[0], gx);
    lstm_rec_fused<0><<<BB / RROWS, 256>>>(gx, Whh[0], nullptr, nullptr, nullptr, bufs[0]);

    // layers 1..4: fused with one-step-shifted ih pipeline
    for (int l = 1; l < 5; l++) {
        const float* hin = bufs[(l - 1) & 1];
        float* ho = bufs[l & 1];
        lstm_rec_fused<1><<<BB / RROWS, 256>>>(hin, Whh[l], Wih[l], bih[l], bhh[l], ho);
    }

    // linear head (layer 4 wrote bufs[0])
    lstm_lin_kernel<<<TT, 256>>>(bufs[0], Wl, bl, out);
}